// round 11
// baseline (speedup 1.0000x reference)
#include <cuda_runtime.h>

// g[b,0,i,j] = cos(phi_i + phi_j) with phi = arccos(c)
//            = c_i*c_j - s_i*s_j,  s = sqrt(1 - c^2)
// c = clamp((2x - mx - mn)/(mx - mn), -1+eps, 1-eps) per batch row.
//
// Single kernel, zero barriers, zero smem. Warp-redundant min/max via
// shuffles; lane l precomputes one row's (ci,si); store loop broadcasts
// them via __shfl_sync: body = 2 SHFL + 8 FMA + STG.128 (.cs).
// Finest grain: 16-row chunks, 16384 CTAs of 128 threads.

#define N 512
#define B 512
#define THREADS 128
#define CHUNKS 32                      // row-chunks per batch
#define ROWS_PER_CHUNK (N / CHUNKS)    // 16

__global__ __launch_bounds__(THREADS)
void gram_kernel(const float* __restrict__ x, float* __restrict__ out) {
    const int b = blockIdx.x;
    const int chunk = blockIdx.y;
    const int tid = threadIdx.x;
    const int lane = tid & 31;

    const float* __restrict__ xb = x + (size_t)b * N;
    const float4* __restrict__ xb4 = (const float4*)xb;

    // Warp-redundant min/max over all 512 floats: 4 lane-strided LDG.128.
    const float4 a0 = __ldg(&xb4[lane]);
    const float4 a1 = __ldg(&xb4[lane + 32]);
    const float4 a2 = __ldg(&xb4[lane + 64]);
    const float4 a3 = __ldg(&xb4[lane + 96]);

    float mn = fminf(fminf(fminf(a0.x, a0.y), fminf(a0.z, a0.w)),
                     fminf(fminf(a1.x, a1.y), fminf(a1.z, a1.w)));
    mn = fminf(mn, fminf(fminf(fminf(a2.x, a2.y), fminf(a2.z, a2.w)),
                         fminf(fminf(a3.x, a3.y), fminf(a3.z, a3.w))));
    float mx = fmaxf(fmaxf(fmaxf(a0.x, a0.y), fmaxf(a0.z, a0.w)),
                     fmaxf(fmaxf(a1.x, a1.y), fmaxf(a1.z, a1.w)));
    mx = fmaxf(mx, fmaxf(fmaxf(fmaxf(a2.x, a2.y), fmaxf(a2.z, a2.w)),
                         fmaxf(fmaxf(a3.x, a3.y), fmaxf(a3.z, a3.w))));
    #pragma unroll
    for (int o = 16; o > 0; o >>= 1) {
        mn = fminf(mn, __shfl_xor_sync(0xFFFFFFFFu, mn, o));
        mx = fmaxf(mx, __shfl_xor_sync(0xFFFFFFFFu, mx, o));
    }

    const float inv = 1.0f / (mx - mn);
    const float shift = mx + mn;
    const float EPS = 1e-6f;

    // This thread's 4 columns (L1-hot re-read): col = tid (0..127)
    const int col = tid;
    const float4 xc = __ldg(&xb4[col]);

    float4 cj, sj;
    cj.x = fminf(fmaxf(fmaf(2.0f, xc.x, -shift) * inv, -1.0f + EPS), 1.0f - EPS);
    cj.y = fminf(fmaxf(fmaf(2.0f, xc.y, -shift) * inv, -1.0f + EPS), 1.0f - EPS);
    cj.z = fminf(fmaxf(fmaf(2.0f, xc.z, -shift) * inv, -1.0f + EPS), 1.0f - EPS);
    cj.w = fminf(fmaxf(fmaf(2.0f, xc.w, -shift) * inv, -1.0f + EPS), 1.0f - EPS);
    sj.x = sqrtf(fmaxf(fmaf(-cj.x, cj.x, 1.0f), 0.0f));
    sj.y = sqrtf(fmaxf(fmaf(-cj.y, cj.y, 1.0f), 0.0f));
    sj.z = sqrtf(fmaxf(fmaf(-cj.z, cj.z, 1.0f), 0.0f));
    sj.w = sqrtf(fmaxf(fmaf(-cj.w, cj.w, 1.0f), 0.0f));

    // Per-lane row precompute: lane l owns row (l & 15) of this chunk.
    const int row0 = chunk * ROWS_PER_CHUNK;
    const float xr = __ldg(&xb[row0 + (lane & 15)]);
    float cr = fminf(fmaxf(fmaf(2.0f, xr, -shift) * inv, -1.0f + EPS), 1.0f - EPS);
    float sr = sqrtf(fmaxf(fmaf(-cr, cr, 1.0f), 0.0f));

    float4* __restrict__ out4 =
        (float4*)(out + (size_t)b * N * N + (size_t)row0 * N);

    // 16 rows per thread; row (ci,si) broadcast from lane k via shuffle.
    #pragma unroll
    for (int k = 0; k < 16; k++) {
        const float ci = __shfl_sync(0xFFFFFFFFu, cr, k);
        const float si = __shfl_sync(0xFFFFFFFFu, sr, k);
        float4 rv;
        rv.x = fmaf(ci, cj.x, -si * sj.x);
        rv.y = fmaf(ci, cj.y, -si * sj.y);
        rv.z = fmaf(ci, cj.z, -si * sj.z);
        rv.w = fmaf(ci, cj.w, -si * sj.w);
        __stcs(&out4[k * 128 + col], rv);
    }
}

extern "C" void kernel_launch(void* const* d_in, const int* in_sizes, int n_in,
                              void* d_out, int out_size) {
    const float* x = (const float*)d_in[0];
    float* out = (float*)d_out;
    dim3 grid(B, CHUNKS);
    gram_kernel<<<grid, THREADS>>>(x, out);
}

// round 12
// speedup vs baseline: 1.0205x; 1.0205x over previous
#include <cuda_runtime.h>

// g[b,0,i,j] = cos(phi_i + phi_j) with phi = arccos(c)
//            = c_i*c_j - s_i*s_j,  s = sqrt(1 - c^2)
// c = clamp((2x - mx - mn)/(mx - mn), -1+eps, 1-eps) per batch row.
//
// Single kernel, zero barriers, zero smem. Warp-redundant min/max via
// shuffles; lane l precomputes one row's (ci,si); store loop broadcasts
// them via __shfl_sync: body = 2 SHFL + 8 FMA + STG.128 (.cs).
// Champion grain: 32-row chunks, 8192 CTAs of 256 threads.
// Grid = (CHUNKS, B) so consecutive CTAs share a batch row (input locality).

#define N 512
#define B 512
#define THREADS 256
#define CHUNKS 16                      // row-chunks per batch
#define ROWS_PER_CHUNK (N / CHUNKS)    // 32

__global__ __launch_bounds__(THREADS)
void gram_kernel(const float* __restrict__ x, float* __restrict__ out) {
    const int chunk = blockIdx.x;
    const int b = blockIdx.y;
    const int tid = threadIdx.x;
    const int lane = tid & 31;

    const float* __restrict__ xb = x + (size_t)b * N;
    const float4* __restrict__ xb4 = (const float4*)xb;

    // Warp-redundant min/max over all 512 floats: 4 lane-strided LDG.128.
    const float4 a0 = __ldg(&xb4[lane]);
    const float4 a1 = __ldg(&xb4[lane + 32]);
    const float4 a2 = __ldg(&xb4[lane + 64]);
    const float4 a3 = __ldg(&xb4[lane + 96]);

    float mn = fminf(fminf(fminf(a0.x, a0.y), fminf(a0.z, a0.w)),
                     fminf(fminf(a1.x, a1.y), fminf(a1.z, a1.w)));
    mn = fminf(mn, fminf(fminf(fminf(a2.x, a2.y), fminf(a2.z, a2.w)),
                         fminf(fminf(a3.x, a3.y), fminf(a3.z, a3.w))));
    float mx = fmaxf(fmaxf(fmaxf(a0.x, a0.y), fmaxf(a0.z, a0.w)),
                     fmaxf(fmaxf(a1.x, a1.y), fmaxf(a1.z, a1.w)));
    mx = fmaxf(mx, fmaxf(fmaxf(fmaxf(a2.x, a2.y), fmaxf(a2.z, a2.w)),
                         fmaxf(fmaxf(a3.x, a3.y), fmaxf(a3.z, a3.w))));
    #pragma unroll
    for (int o = 16; o > 0; o >>= 1) {
        mn = fminf(mn, __shfl_xor_sync(0xFFFFFFFFu, mn, o));
        mx = fmaxf(mx, __shfl_xor_sync(0xFFFFFFFFu, mx, o));
    }

    const float inv = 1.0f / (mx - mn);
    const float shift = mx + mn;
    const float EPS = 1e-6f;

    // This thread's 4 columns (L1-hot re-read)
    const int col  = tid & 127;          // float4 column group 0..127
    const int half = tid >> 7;           // row parity 0/1 (uniform per warp)
    const float4 xc = __ldg(&xb4[col]);

    float4 cj, sj;
    cj.x = fminf(fmaxf(fmaf(2.0f, xc.x, -shift) * inv, -1.0f + EPS), 1.0f - EPS);
    cj.y = fminf(fmaxf(fmaf(2.0f, xc.y, -shift) * inv, -1.0f + EPS), 1.0f - EPS);
    cj.z = fminf(fmaxf(fmaf(2.0f, xc.z, -shift) * inv, -1.0f + EPS), 1.0f - EPS);
    cj.w = fminf(fmaxf(fmaf(2.0f, xc.w, -shift) * inv, -1.0f + EPS), 1.0f - EPS);
    sj.x = sqrtf(fmaxf(fmaf(-cj.x, cj.x, 1.0f), 0.0f));
    sj.y = sqrtf(fmaxf(fmaf(-cj.y, cj.y, 1.0f), 0.0f));
    sj.z = sqrtf(fmaxf(fmaf(-cj.z, cj.z, 1.0f), 0.0f));
    sj.w = sqrtf(fmaxf(fmaf(-cj.w, cj.w, 1.0f), 0.0f));

    // Per-lane row precompute: lane l owns row (half + 2*(l&15)) of this chunk.
    const int row0 = chunk * ROWS_PER_CHUNK;
    const float xr = __ldg(&xb[row0 + half + 2 * (lane & 15)]);
    float cr = fminf(fmaxf(fmaf(2.0f, xr, -shift) * inv, -1.0f + EPS), 1.0f - EPS);
    float sr = sqrtf(fmaxf(fmaf(-cr, cr, 1.0f), 0.0f));

    float4* __restrict__ out4 =
        (float4*)(out + (size_t)b * N * N + (size_t)row0 * N);

    // 16 rows per thread, processed as 8 interleaved pairs to overlap the
    // SHFL -> FMA -> STG chains of two rows.
    #pragma unroll
    for (int k = 0; k < 16; k += 2) {
        const float ci0 = __shfl_sync(0xFFFFFFFFu, cr, k);
        const float si0 = __shfl_sync(0xFFFFFFFFu, sr, k);
        const float ci1 = __shfl_sync(0xFFFFFFFFu, cr, k + 1);
        const float si1 = __shfl_sync(0xFFFFFFFFu, sr, k + 1);
        const int r0 = half + 2 * k;
        const int r1 = half + 2 * (k + 1);
        float4 v0, v1;
        v0.x = fmaf(ci0, cj.x, -si0 * sj.x);
        v1.x = fmaf(ci1, cj.x, -si1 * sj.x);
        v0.y = fmaf(ci0, cj.y, -si0 * sj.y);
        v1.y = fmaf(ci1, cj.y, -si1 * sj.y);
        v0.z = fmaf(ci0, cj.z, -si0 * sj.z);
        v1.z = fmaf(ci1, cj.z, -si1 * sj.z);
        v0.w = fmaf(ci0, cj.w, -si0 * sj.w);
        v1.w = fmaf(ci1, cj.w, -si1 * sj.w);
        __stcs(&out4[r0 * 128 + col], v0);
        __stcs(&out4[r1 * 128 + col], v1);
    }
}

extern "C" void kernel_launch(void* const* d_in, const int* in_sizes, int n_in,
                              void* d_out, int out_size) {
    const float* x = (const float*)d_in[0];
    float* out = (float*)d_out;
    dim3 grid(CHUNKS, B);
    gram_kernel<<<grid, THREADS>>>(x, out);
}